// round 5
// baseline (speedup 1.0000x reference)
#include <cuda_runtime.h>

#define B_ROWS 16384
#define HID 256
#define COMP 32
#define T_TOK 8
#define NVOC 257
#define VSTRIDE 261          // padded row stride for sorted vocab (bank-spread)
#define NF 0.0625f
#define EPS_THR 1e-6f
#define NGROUP 2048
#define ROWS_PB 16

typedef unsigned long long u64;

// ---- packed fp32x2 helpers (sm_103a FFMA2 path; ptxas never auto-fuses) ----
__device__ __forceinline__ u64 pk(float lo, float hi) {
    u64 r; asm("mov.b64 %0,{%1,%2};" : "=l"(r) : "f"(lo), "f"(hi)); return r;
}
__device__ __forceinline__ void ffma2(u64& d, u64 a, u64 b) {
    asm("fma.rn.f32x2 %0,%1,%2,%0;" : "+l"(d) : "l"(a), "l"(b));
}
__device__ __forceinline__ float upk_sum(u64 v) {
    float lo, hi; asm("mov.b64 {%0,%1},%2;" : "=f"(lo), "=f"(hi) : "l"(v));
    return lo + hi;
}
// one LDS.128 -> two packed f32x2 operands, no pack MOVs
__device__ __forceinline__ void lds2(u64& a, u64& b, unsigned addr) {
    asm("ld.shared.v2.u64 {%0,%1},[%2];" : "=l"(a), "=l"(b) : "r"(addr));
}

// ---------------- device scratch (no allocations allowed) ----------------
__device__ float g_msg[B_ROWS * HID];
__device__ float g_vocs[COMP * VSTRIDE];   // per-dim sorted vocab columns

// ---------------- Kernel 0: per-dim bitonic sort of vocab columns ---------
__global__ __launch_bounds__(512) void sort_kernel(const float* __restrict__ vocab)
{
    __shared__ float buf[512];
    const int d = blockIdx.x;
    const int t = threadIdx.x;
    buf[t] = (t < NVOC) ? vocab[t * COMP + d] : 1e30f;
    __syncthreads();
    for (int k = 2; k <= 512; k <<= 1) {
        for (int j = k >> 1; j > 0; j >>= 1) {
            int ixj = t ^ j;
            if (ixj > t) {
                float a = buf[t], b = buf[ixj];
                bool up = ((t & k) == 0);
                if ((a > b) == up) { buf[t] = b; buf[ixj] = a; }
            }
            __syncthreads();
        }
    }
    if (t < NVOC) g_vocs[d * VSTRIDE + t] = buf[t];
}

// branchless lower-bound nearest-neighbor squared distance (bitwise identical
// to the full 257-entry per-dim min scan; see round-2 derivation).
__device__ __forceinline__ float nearest_sq(const float* __restrict__ arr, float x)
{
    int p = 0;
    #pragma unroll
    for (int s = 256; s; s >>= 1) {
        int q = p + s;
        if (q <= NVOC) { if (arr[q - 1] <= x) p = q; }
    }
    float lo = (p > 0)    ? arr[p - 1] : 1e30f;
    float hi = (p < NVOC) ? arr[p]     : 1e30f;
    float a = x - lo, b = x - hi;
    return fminf(a * a, b * b);
}

// ---------------- Kernel 1: persistent fused main kernel -------------------
// 16 rows/block, 256 threads, 3 blocks/SM (85-reg budget; GEMMs pass-split
// into 8-row halves so the live accumulator set fits without spills).
// smem layout identical to round 2: 18288 floats = 73152 B, x3 = 219 KB/SM.
__global__ void __launch_bounds__(256, 3) main_kernel(
    const float* __restrict__ hs,
    const float* __restrict__ WQ, const float* __restrict__ bQ,
    const float* __restrict__ WK, const float* __restrict__ bK,
    const float* __restrict__ Wmu, const float* __restrict__ bmu,
    const float* __restrict__ Wvar, const float* __restrict__ bvar,
    const float* __restrict__ vocab, const float* __restrict__ eps)
{
    extern __shared__ float sm[];
    float* ha_s   = sm;
    float* msg_s  = sm + 4096;
    float* vocs_s = sm + 8192;
    float* mulv_s = sm + 16544;
    float* tok_s  = sm + 17568;
    float* eos_s  = sm + 18080;
    float* maskf  = sm + 18112;
    float* fin_s  = sm + 18128;
    float* inv_s  = sm + 18144;
    float* part_s = sm + 18160;

    const int t = threadIdx.x;
    const int r0 = blockIdx.x * ROWS_PB;
    const int w = t >> 5, l = t & 31;
    const unsigned ha_sa  = (unsigned)__cvta_generic_to_shared(ha_s);
    const unsigned tok_sa = (unsigned)__cvta_generic_to_shared(tok_s);

    // ---- block-resident setup ----
    for (int i = t; i < COMP * VSTRIDE; i += 256) vocs_s[i] = g_vocs[i];
    if (t < COMP) eos_s[t] = vocab[256 * COMP + t];
    if (t < ROWS_PB) { maskf[t] = 1.0f; fin_s[t] = 0.0f; }
    {
        const float4* src = (const float4*)(hs + (size_t)r0 * HID);
        float4* dst = (float4*)ha_s;
        for (int i = t; i < ROWS_PB * HID / 4; i += 256) dst[i] = src[i];
    }
    __syncthreads();

    // ---- Q = (hs@WQ+bQ)*NF ; V = hs@WK+bK  (packed FFMA2, 2 passes of 8 rows)
    float Qr[16], Vr[16], kacc[16];
    {
        const float bq = bQ[t], bk = bK[t];
        #pragma unroll 1
        for (int h = 0; h < 2; h++) {
            const int mb = h * 8;
            u64 aq[8], av[8];
            #pragma unroll
            for (int m = 0; m < 8; m++) { aq[m] = pk(bq, 0.0f); av[m] = pk(bk, 0.0f); }
            #pragma unroll 2
            for (int k = 0; k < HID; k += 4) {
                float q0 = WQ[(k+0)*HID+t], q1 = WQ[(k+1)*HID+t];
                float q2 = WQ[(k+2)*HID+t], q3 = WQ[(k+3)*HID+t];
                float v0 = WK[(k+0)*HID+t], v1 = WK[(k+1)*HID+t];
                float v2 = WK[(k+2)*HID+t], v3 = WK[(k+3)*HID+t];
                u64 wq01 = pk(q0, q1), wq23 = pk(q2, q3);
                u64 wv01 = pk(v0, v1), wv23 = pk(v2, v3);
                #pragma unroll
                for (int m = 0; m < 8; m++) {
                    u64 a01, a23;
                    lds2(a01, a23, ha_sa + (unsigned)(((mb + m) * HID + k) * 4));
                    ffma2(aq[m], a01, wq01); ffma2(aq[m], a23, wq23);
                    ffma2(av[m], a01, wv01); ffma2(av[m], a23, wv23);
                }
            }
            #pragma unroll
            for (int m = 0; m < 8; m++) {
                Qr[mb + m] = upk_sum(aq[m]) * NF;
                Vr[mb + m] = upk_sum(av[m]);
                kacc[mb + m] = bk;
            }
        }
    }

    // ---- token recurrence ----
    #pragma unroll 1
    for (int it = 0; it < T_TOK; it++) {
        __syncthreads();

        // Phase 1: incremental K update with previous token (2 passes of 8 rows)
        if (it > 0) {
            const float* wkp = WK + (size_t)((it - 1) * COMP) * HID + t;
            #pragma unroll 1
            for (int h = 0; h < 2; h++) {
                const int mb = h * 8;
                u64 acc2[8];
                #pragma unroll
                for (int m = 0; m < 8; m++) acc2[m] = 0ull;
                #pragma unroll
                for (int c = 0; c < COMP; c += 4) {
                    float w0 = wkp[(c+0)*HID], w1 = wkp[(c+1)*HID];
                    float w2 = wkp[(c+2)*HID], w3 = wkp[(c+3)*HID];
                    u64 w01 = pk(w0, w1), w23 = pk(w2, w3);
                    #pragma unroll
                    for (int m = 0; m < 8; m++) {
                        u64 a01, a23;
                        lds2(a01, a23, tok_sa + (unsigned)(((mb + m) * COMP + c) * 4));
                        ffma2(acc2[m], a01, w01); ffma2(acc2[m], a23, w23);
                    }
                }
                #pragma unroll
                for (int m = 0; m < 8; m++) kacc[mb + m] += upk_sum(acc2[m]);
            }
        }

        // Phase 2: e = exp(-(Q*K)); write e*V to ha_s; per-row partial sums
        #pragma unroll
        for (int m = 0; m < 16; m++) {
            float e = __expf(-(Qr[m] * (kacc[m] * NF)));
            ha_s[m * HID + t] = e * Vr[m];
            float s = e;
            #pragma unroll
            for (int o = 16; o; o >>= 1) s += __shfl_xor_sync(0xffffffffu, s, o);
            if (l == 0) part_s[m * 8 + w] = s;
        }
        __syncthreads();
        if (t < 16) {
            float s = 0.0f;
            #pragma unroll
            for (int ww = 0; ww < 8; ww++) s += part_s[t * 8 + ww];
            inv_s[t] = 1.0f / s;
        }
        __syncthreads();

        // Phase 3a: raw (e*V) @ [Wmu|Wvar], packed FFMA2; thread owns 1 output
        // col over a 64-wide k-partition; 2 passes of 8 rows (reg pressure)
        {
            const int c  = t & 63;
            const int kp = t >> 6;
            const float* Wcol = (c < 32) ? (Wmu + c) : (Wvar + (c - 32));
            const int k0 = kp * 64;
            float res[16];
            #pragma unroll 1
            for (int h = 0; h < 2; h++) {
                const int mb = h * 8;
                u64 acc2[8];
                #pragma unroll
                for (int m = 0; m < 8; m++) acc2[m] = 0ull;
                #pragma unroll 2
                for (int k = k0; k < k0 + 64; k += 4) {
                    float w0 = Wcol[(size_t)(k+0)*COMP], w1 = Wcol[(size_t)(k+1)*COMP];
                    float w2 = Wcol[(size_t)(k+2)*COMP], w3 = Wcol[(size_t)(k+3)*COMP];
                    u64 w01 = pk(w0, w1), w23 = pk(w2, w3);
                    #pragma unroll
                    for (int m = 0; m < 8; m++) {
                        u64 a01, a23;
                        lds2(a01, a23, ha_sa + (unsigned)(((mb + m) * HID + k) * 4));
                        ffma2(acc2[m], a01, w01); ffma2(acc2[m], a23, w23);
                    }
                }
                #pragma unroll
                for (int m = 0; m < 8; m++) res[mb + m] = upk_sum(acc2[m]);
            }
            __syncthreads();   // all ha_s reads done -> reuse as staging
            #pragma unroll
            for (int m = 0; m < 16; m++) ha_s[kp * 1024 + m * 64 + c] = res[m];
        }
        __syncthreads();
        // reduce 4 k-partitions -> mulv_s[m][c]
        {
            float4 s = ((const float4*)ha_s)[t];
            #pragma unroll
            for (int kp = 1; kp < 4; kp++) {
                float4 b = ((const float4*)ha_s)[kp * 256 + t];
                s.x += b.x; s.y += b.y; s.z += b.z; s.w += b.w;
            }
            ((float4*)mulv_s)[t] = s;
        }
        __syncthreads();

        // Phase 3b: normalize, bias, sample, nearest-vocab sq dist, mask
        {
            const int m  = t >> 4;
            const int c0 = (t & 15) * 2;
            const float iv = inv_s[m];
            float2 rmu = *(const float2*)&mulv_s[m * 64 + c0];
            float2 rlv = *(const float2*)&mulv_s[m * 64 + 32 + c0];
            float2 bm  = *(const float2*)&bmu[c0];
            float2 bv  = *(const float2*)&bvar[c0];
            float amu0 = rmu.x * iv + bm.x, amu1 = rmu.y * iv + bm.y;
            float alv0 = rlv.x * iv + bv.x, alv1 = rlv.y * iv + bv.y;
            const size_t r = (size_t)(r0 + m);
            const float* ep = eps + ((size_t)it * B_ROWS + r) * COMP + c0;
            float2 e2 = *(const float2*)ep;
            float x0 = e2.x * __expf(0.5f * alv0) + amu0;
            float x1 = e2.y * __expf(0.5f * alv1) + amu1;
            float d0 = nearest_sq(vocs_s + c0 * VSTRIDE, x0);
            float d1 = nearest_sq(vocs_s + (c0 + 1) * VSTRIDE, x1);
            const float mk = maskf[m];
            tok_s[m * COMP + c0]     = d0 * mk;
            tok_s[m * COMP + c0 + 1] = d1 * mk;
        }
        __syncthreads();

        // Phase 4: EOS / repeat-hit logic -> final token into tok_s + msg_s
        {
            #pragma unroll
            for (int mm = 0; mm < 2; mm++) {
                const int m = w * 2 + mm;
                float tk = tok_s[m * COMP + l];
                float ev = eos_s[l];
                float de = tk - ev;
                float se = de * de;
                #pragma unroll
                for (int o = 16; o; o >>= 1) se += __shfl_xor_sync(0xffffffffu, se, o);
                bool hit = (se < EPS_THR);
                for (int p = 0; p < it; p++) {
                    float dp = tk - msg_s[m * HID + p * COMP + l];
                    float sp = dp * dp;
                    #pragma unroll
                    for (int o = 16; o; o >>= 1) sp += __shfl_xor_sync(0xffffffffu, sp, o);
                    hit = hit || (sp < EPS_THR);
                }
                float fin = fin_s[m];
                bool new_eos = hit && (fin == 0.0f);
                float outv = new_eos ? ev : tk;
                msg_s[m * HID + it * COMP + l] = outv;
                tok_s[m * COMP + l] = outv;
                if (l == 0 && hit) { maskf[m] = 0.0f; fin_s[m] = 1.0f; }
            }
        }
    }

    // ---- flush message to global for the tail ----
    __syncthreads();
    {
        float4* dst = (float4*)(g_msg + (size_t)r0 * HID);
        const float4* src = (const float4*)msg_s;
        for (int i = t; i < ROWS_PB * HID / 4; i += 256) dst[i] = src[i];
    }
}

// ---------------- Kernel 2: fused tail: group-sum/7 @Wsum -> @Whead+relu ---
__global__ __launch_bounds__(256) void tail_kernel(
    const float* __restrict__ Wsum, const float* __restrict__ bsum,
    const float* __restrict__ Whead, const float* __restrict__ bhead,
    float* __restrict__ out)
{
    __shared__ __align__(16) float A_s[16 * HID];
    const int t = threadIdx.x;
    const int g0 = blockIdx.x * 16;
    const unsigned A_sa = (unsigned)__cvta_generic_to_shared(A_s);

    #pragma unroll
    for (int m = 0; m < 16; m++) {
        float s = 0.0f;
        #pragma unroll
        for (int a = 0; a < 8; a++)
            s += g_msg[(size_t)((g0 + m) * 8 + a) * HID + t];
        A_s[m * HID + t] = s * (1.0f / 7.0f);
    }
    __syncthreads();

    float res[16];
    {
        u64 acc2[16];
        const float bb = bsum[t];
        #pragma unroll
        for (int m = 0; m < 16; m++) acc2[m] = pk(bb, 0.0f);
        #pragma unroll 2
        for (int k = 0; k < HID; k += 4) {
            float w0 = Wsum[(k+0)*HID+t], w1 = Wsum[(k+1)*HID+t];
            float w2 = Wsum[(k+2)*HID+t], w3 = Wsum[(k+3)*HID+t];
            u64 w01 = pk(w0, w1), w23 = pk(w2, w3);
            #pragma unroll
            for (int m = 0; m < 16; m++) {
                u64 a01, a23;
                lds2(a01, a23, A_sa + (unsigned)((m * HID + k) * 4));
                ffma2(acc2[m], a01, w01); ffma2(acc2[m], a23, w23);
            }
        }
        #pragma unroll
        for (int m = 0; m < 16; m++) res[m] = upk_sum(acc2[m]);
    }
    __syncthreads();
    #pragma unroll
    for (int m = 0; m < 16; m++) A_s[m * HID + t] = res[m];
    __syncthreads();

    {
        u64 acc2[16];
        const float bb = bhead[t];
        #pragma unroll
        for (int m = 0; m < 16; m++) acc2[m] = pk(bb, 0.0f);
        #pragma unroll 2
        for (int k = 0; k < HID; k += 4) {
            float w0 = Whead[(k+0)*HID+t], w1 = Whead[(k+1)*HID+t];
            float w2 = Whead[(k+2)*HID+t], w3 = Whead[(k+3)*HID+t];
            u64 w01 = pk(w0, w1), w23 = pk(w2, w3);
            #pragma unroll
            for (int m = 0; m < 16; m++) {
                u64 a01, a23;
                lds2(a01, a23, A_sa + (unsigned)((m * HID + k) * 4));
                ffma2(acc2[m], a01, w01); ffma2(acc2[m], a23, w23);
            }
        }
        #pragma unroll
        for (int m = 0; m < 16; m++) res[m] = upk_sum(acc2[m]);
    }
    #pragma unroll
    for (int m = 0; m < 16; m++) {
        float v = fmaxf(res[m], 0.0f);
        #pragma unroll
        for (int a = 0; a < 8; a++)
            out[(size_t)((g0 + m) * 8 + a) * HID + t] = v;
    }
}

// ---------------- launch ---------------------------------------------------
extern "C" void kernel_launch(void* const* d_in, const int* in_sizes, int n_in,
                              void* d_out, int out_size)
{
    const float* hs    = (const float*)d_in[0];
    const float* eps   = (const float*)d_in[1];
    const float* WQ    = (const float*)d_in[2];
    const float* bQ    = (const float*)d_in[3];
    const float* WK    = (const float*)d_in[4];
    const float* bK    = (const float*)d_in[5];
    const float* Wmu   = (const float*)d_in[6];
    const float* bmu   = (const float*)d_in[7];
    const float* Wvar  = (const float*)d_in[8];
    const float* bvar  = (const float*)d_in[9];
    const float* vocab = (const float*)d_in[10];
    const float* Wsum  = (const float*)d_in[11];
    const float* bsum  = (const float*)d_in[12];
    const float* Whead = (const float*)d_in[13];
    const float* bhead = (const float*)d_in[14];
    float* out = (float*)d_out;

    const int smem_main = 18288 * (int)sizeof(float);   // 73152 B
    cudaFuncSetAttribute(main_kernel,
                         cudaFuncAttributeMaxDynamicSharedMemorySize, smem_main);

    sort_kernel<<<COMP, 512>>>(vocab);
    main_kernel<<<B_ROWS / ROWS_PB, 256, smem_main>>>(
        hs, WQ, bQ, WK, bK, Wmu, bmu, Wvar, bvar, vocab, eps);
    tail_kernel<<<NGROUP / 16, 256>>>(Wsum, bsum, Whead, bhead, out);
}

// round 6
// speedup vs baseline: 1.0209x; 1.0209x over previous
#include <cuda_runtime.h>

#define B_ROWS 16384
#define HID 256
#define COMP 32
#define T_TOK 8
#define NVOC 257
#define VSTRIDE 261          // padded row stride for sorted vocab (bank-spread)
#define NF 0.0625f
#define EPS_THR 1e-6f
#define NGROUP 2048
#define ROWS_PB 8

typedef unsigned long long u64;

// ---- packed fp32x2 helpers (sm_103a FFMA2 path; ptxas never auto-fuses) ----
__device__ __forceinline__ u64 pk(float lo, float hi) {
    u64 r; asm("mov.b64 %0,{%1,%2};" : "=l"(r) : "f"(lo), "f"(hi)); return r;
}
__device__ __forceinline__ void ffma2(u64& d, u64 a, u64 b) {
    asm("fma.rn.f32x2 %0,%1,%2,%0;" : "+l"(d) : "l"(a), "l"(b));
}
__device__ __forceinline__ float upk_sum(u64 v) {
    float lo, hi; asm("mov.b64 {%0,%1},%2;" : "=f"(lo), "=f"(hi) : "l"(v));
    return lo + hi;
}
// one LDS.128 -> two packed f32x2 operands, no pack MOVs
__device__ __forceinline__ void lds2(u64& a, u64& b, unsigned addr) {
    asm("ld.shared.v2.u64 {%0,%1},[%2];" : "=l"(a), "=l"(b) : "r"(addr));
}

// ---------------- device scratch (no allocations allowed) ----------------
__device__ float g_msg[B_ROWS * HID];
__device__ float g_vocs[COMP * VSTRIDE];   // per-dim sorted vocab columns

// ---------------- Kernel 0: per-dim bitonic sort of vocab columns ---------
__global__ __launch_bounds__(512) void sort_kernel(const float* __restrict__ vocab)
{
    __shared__ float buf[512];
    const int d = blockIdx.x;
    const int t = threadIdx.x;
    buf[t] = (t < NVOC) ? vocab[t * COMP + d] : 1e30f;
    __syncthreads();
    for (int k = 2; k <= 512; k <<= 1) {
        for (int j = k >> 1; j > 0; j >>= 1) {
            int ixj = t ^ j;
            if (ixj > t) {
                float a = buf[t], b = buf[ixj];
                bool up = ((t & k) == 0);
                if ((a > b) == up) { buf[t] = b; buf[ixj] = a; }
            }
            __syncthreads();
        }
    }
    if (t < NVOC) g_vocs[d * VSTRIDE + t] = buf[t];
}

// branchless lower-bound nearest-neighbor squared distance (bitwise identical
// to the full 257-entry per-dim min scan; see round-2 derivation).
__device__ __forceinline__ float nearest_sq(const float* __restrict__ arr, float x)
{
    int p = 0;
    #pragma unroll
    for (int s = 256; s; s >>= 1) {
        int q = p + s;
        if (q <= NVOC) { if (arr[q - 1] <= x) p = q; }
    }
    float lo = (p > 0)    ? arr[p - 1] : 1e30f;
    float hi = (p < NVOC) ? arr[p]     : 1e30f;
    float a = x - lo, b = x - hi;
    return fminf(a * a, b * b);
}

// ---------------- Kernel 1: persistent fused main kernel -------------------
// 8 rows/block, 256 threads, 3 blocks/SM (85-reg budget; ~75 live regs max,
// no pass-splitting -> no spills). smem (floats):
//   ha_s   [8*256]  0      (hs tile at init; e*V per iter; GEMM staging)
//   msg_s  [8*256]  2048
//   vocs_s [32*261] 4096
//   tok_s  [8*32]   12448
//   eos_s  [32]     12704
//   maskf  [8]      12736
//   fin_s  [8]      12744
//   part_s [8*8]    12752
// total 12816 floats = 51264 B, x3 = 154 KB/SM.
__global__ void __launch_bounds__(256, 3) main_kernel(
    const float* __restrict__ hs,
    const float* __restrict__ WQ, const float* __restrict__ bQ,
    const float* __restrict__ WK, const float* __restrict__ bK,
    const float* __restrict__ Wmu, const float* __restrict__ bmu,
    const float* __restrict__ Wvar, const float* __restrict__ bvar,
    const float* __restrict__ vocab, const float* __restrict__ eps)
{
    extern __shared__ float sm[];
    float* ha_s   = sm;
    float* msg_s  = sm + 2048;
    float* vocs_s = sm + 4096;
    float* tok_s  = sm + 12448;
    float* eos_s  = sm + 12704;
    float* maskf  = sm + 12736;
    float* fin_s  = sm + 12744;
    float* part_s = sm + 12752;

    const int t = threadIdx.x;
    const int r0 = blockIdx.x * ROWS_PB;
    const int w = t >> 5, l = t & 31;
    const unsigned ha_sa  = (unsigned)__cvta_generic_to_shared(ha_s);
    const unsigned tok_sa = (unsigned)__cvta_generic_to_shared(tok_s);

    // ---- block-resident setup ----
    for (int i = t; i < COMP * VSTRIDE; i += 256) vocs_s[i] = g_vocs[i];
    if (t < COMP) eos_s[t] = vocab[256 * COMP + t];
    if (t < ROWS_PB) { maskf[t] = 1.0f; fin_s[t] = 0.0f; }
    {
        const float4* src = (const float4*)(hs + (size_t)r0 * HID);
        float4* dst = (float4*)ha_s;
        for (int i = t; i < ROWS_PB * HID / 4; i += 256) dst[i] = src[i];
    }
    __syncthreads();

    // ---- Q = (hs@WQ+bQ)*NF ; V = hs@WK+bK  (packed FFMA2 GEMM, 8 rows) ----
    float Qr[8], Vr[8], kacc[8];
    {
        const float bq = bQ[t], bk = bK[t];
        u64 aq[8], av[8];
        #pragma unroll
        for (int m = 0; m < 8; m++) { aq[m] = pk(bq, 0.0f); av[m] = pk(bk, 0.0f); }
        #pragma unroll 2
        for (int k = 0; k < HID; k += 4) {
            float q0 = WQ[(k+0)*HID+t], q1 = WQ[(k+1)*HID+t];
            float q2 = WQ[(k+2)*HID+t], q3 = WQ[(k+3)*HID+t];
            float v0 = WK[(k+0)*HID+t], v1 = WK[(k+1)*HID+t];
            float v2 = WK[(k+2)*HID+t], v3 = WK[(k+3)*HID+t];
            u64 wq01 = pk(q0, q1), wq23 = pk(q2, q3);
            u64 wv01 = pk(v0, v1), wv23 = pk(v2, v3);
            #pragma unroll
            for (int m = 0; m < 8; m++) {
                u64 a01, a23;
                lds2(a01, a23, ha_sa + (unsigned)((m * HID + k) * 4));
                ffma2(aq[m], a01, wq01); ffma2(aq[m], a23, wq23);
                ffma2(av[m], a01, wv01); ffma2(av[m], a23, wv23);
            }
        }
        #pragma unroll
        for (int m = 0; m < 8; m++) {
            Qr[m] = upk_sum(aq[m]) * NF;
            Vr[m] = upk_sum(av[m]);
            kacc[m] = bk;
        }
    }

    // ---- token recurrence ----
    #pragma unroll 1
    for (int it = 0; it < T_TOK; it++) {
        __syncthreads();   // A: orders prev phase4 writes (tok/msg/mask/fin)

        // Phase 1: incremental K update with previous token (32 new msg cols)
        if (it > 0) {
            const float* wkp = WK + (size_t)((it - 1) * COMP) * HID + t;
            u64 acc2[8];
            #pragma unroll
            for (int m = 0; m < 8; m++) acc2[m] = 0ull;
            #pragma unroll
            for (int c = 0; c < COMP; c += 4) {
                float w0 = wkp[(c+0)*HID], w1 = wkp[(c+1)*HID];
                float w2 = wkp[(c+2)*HID], w3 = wkp[(c+3)*HID];
                u64 w01 = pk(w0, w1), w23 = pk(w2, w3);
                #pragma unroll
                for (int m = 0; m < 8; m++) {
                    u64 a01, a23;
                    lds2(a01, a23, tok_sa + (unsigned)((m * COMP + c) * 4));
                    ffma2(acc2[m], a01, w01); ffma2(acc2[m], a23, w23);
                }
            }
            #pragma unroll
            for (int m = 0; m < 8; m++) kacc[m] += upk_sum(acc2[m]);
        }

        // Phase 2: e = exp(-(Q*K)); write e*V to ha_s; per-row partial sums
        #pragma unroll
        for (int m = 0; m < 8; m++) {
            float e = __expf(-(Qr[m] * (kacc[m] * NF)));
            ha_s[m * HID + t] = e * Vr[m];
            float s = e;
            #pragma unroll
            for (int o = 16; o; o >>= 1) s += __shfl_xor_sync(0xffffffffu, s, o);
            if (l == 0) part_s[m * 8 + w] = s;
        }
        __syncthreads();   // B: ha_s + part_s visible

        // Phase 3a: raw (e*V) @ [Wmu|Wvar], packed FFMA2; thread owns 1 output
        // col for all 8 rows over a 64-wide k-partition
        {
            const int c  = t & 63;
            const int kp = t >> 6;
            const float* Wcol = (c < 32) ? (Wmu + c) : (Wvar + (c - 32));
            const int k0 = kp * 64;
            u64 acc2[8];
            #pragma unroll
            for (int m = 0; m < 8; m++) acc2[m] = 0ull;
            #pragma unroll 2
            for (int k = k0; k < k0 + 64; k += 4) {
                float w0 = Wcol[(size_t)(k+0)*COMP], w1 = Wcol[(size_t)(k+1)*COMP];
                float w2 = Wcol[(size_t)(k+2)*COMP], w3 = Wcol[(size_t)(k+3)*COMP];
                u64 w01 = pk(w0, w1), w23 = pk(w2, w3);
                #pragma unroll
                for (int m = 0; m < 8; m++) {
                    u64 a01, a23;
                    lds2(a01, a23, ha_sa + (unsigned)((m * HID + k) * 4));
                    ffma2(acc2[m], a01, w01); ffma2(acc2[m], a23, w23);
                }
            }
            __syncthreads();   // D: all ha_s reads done -> reuse as staging
            #pragma unroll
            for (int m = 0; m < 8; m++)
                ha_s[kp * 512 + m * 64 + c] = upk_sum(acc2[m]);
        }
        __syncthreads();   // E: staging visible

        // Phase 3b: inline kp-reduce + inv + bias, sample, nearest-vocab, mask
        {
            const int m = t >> 5;
            const int c = t & 31;
            float smu = 0.0f, slv = 0.0f;
            #pragma unroll
            for (int kp = 0; kp < 4; kp++) {
                smu += ha_s[kp * 512 + m * 64 + c];
                slv += ha_s[kp * 512 + m * 64 + 32 + c];
            }
            float rs = 0.0f;
            #pragma unroll
            for (int ww = 0; ww < 8; ww++) rs += part_s[m * 8 + ww];
            const float iv = 1.0f / rs;
            float amu = smu * iv + bmu[c];
            float alv = slv * iv + bvar[c];
            const size_t r = (size_t)(r0 + m);
            float e = eps[((size_t)it * B_ROWS + r) * COMP + c];
            float x = e * __expf(0.5f * alv) + amu;
            float d = nearest_sq(vocs_s + c * VSTRIDE, x);
            tok_s[m * COMP + c] = d * maskf[m];
        }
        __syncthreads();   // G: tok_s visible

        // Phase 4: EOS / repeat-hit logic; warp w owns row w, lane = comp dim
        {
            float tk = tok_s[w * COMP + l];
            float ev = eos_s[l];
            float de = tk - ev;
            float se = de * de;
            #pragma unroll
            for (int o = 16; o; o >>= 1) se += __shfl_xor_sync(0xffffffffu, se, o);
            bool hit = (se < EPS_THR);
            for (int p = 0; p < it; p++) {
                float dp = tk - msg_s[w * HID + p * COMP + l];
                float sp = dp * dp;
                #pragma unroll
                for (int o = 16; o; o >>= 1) sp += __shfl_xor_sync(0xffffffffu, sp, o);
                hit = hit || (sp < EPS_THR);
            }
            float fin = fin_s[w];
            bool new_eos = hit && (fin == 0.0f);
            float outv = new_eos ? ev : tk;
            msg_s[w * HID + it * COMP + l] = outv;
            tok_s[w * COMP + l] = outv;
            if (l == 0 && hit) { maskf[w] = 0.0f; fin_s[w] = 1.0f; }
        }
    }

    // ---- flush message to global for the tail ----
    __syncthreads();
    {
        float4* dst = (float4*)(g_msg + (size_t)r0 * HID);
        const float4* src = (const float4*)msg_s;
        for (int i = t; i < ROWS_PB * HID / 4; i += 256) dst[i] = src[i];
    }
}

// ---------------- Kernel 2: fused tail: group-sum/7 @Wsum -> @Whead+relu ---
__global__ __launch_bounds__(256) void tail_kernel(
    const float* __restrict__ Wsum, const float* __restrict__ bsum,
    const float* __restrict__ Whead, const float* __restrict__ bhead,
    float* __restrict__ out)
{
    __shared__ __align__(16) float A_s[16 * HID];
    const int t = threadIdx.x;
    const int g0 = blockIdx.x * 16;
    const unsigned A_sa = (unsigned)__cvta_generic_to_shared(A_s);

    #pragma unroll
    for (int m = 0; m < 16; m++) {
        float s = 0.0f;
        #pragma unroll
        for (int a = 0; a < 8; a++)
            s += g_msg[(size_t)((g0 + m) * 8 + a) * HID + t];
        A_s[m * HID + t] = s * (1.0f / 7.0f);
    }
    __syncthreads();

    float res[16];
    {
        u64 acc2[16];
        const float bb = bsum[t];
        #pragma unroll
        for (int m = 0; m < 16; m++) acc2[m] = pk(bb, 0.0f);
        #pragma unroll 2
        for (int k = 0; k < HID; k += 4) {
            float w0 = Wsum[(k+0)*HID+t], w1 = Wsum[(k+1)*HID+t];
            float w2 = Wsum[(k+2)*HID+t], w3 = Wsum[(k+3)*HID+t];
            u64 w01 = pk(w0, w1), w23 = pk(w2, w3);
            #pragma unroll
            for (int m = 0; m < 16; m++) {
                u64 a01, a23;
                lds2(a01, a23, A_sa + (unsigned)((m * HID + k) * 4));
                ffma2(acc2[m], a01, w01); ffma2(acc2[m], a23, w23);
            }
        }
        #pragma unroll
        for (int m = 0; m < 16; m++) res[m] = upk_sum(acc2[m]);
    }
    __syncthreads();
    #pragma unroll
    for (int m = 0; m < 16; m++) A_s[m * HID + t] = res[m];
    __syncthreads();

    {
        u64 acc2[16];
        const float bb = bhead[t];
        #pragma unroll
        for (int m = 0; m < 16; m++) acc2[m] = pk(bb, 0.0f);
        #pragma unroll 2
        for (int k = 0; k < HID; k += 4) {
            float w0 = Whead[(k+0)*HID+t], w1 = Whead[(k+1)*HID+t];
            float w2 = Whead[(k+2)*HID+t], w3 = Whead[(k+3)*HID+t];
            u64 w01 = pk(w0, w1), w23 = pk(w2, w3);
            #pragma unroll
            for (int m = 0; m < 16; m++) {
                u64 a01, a23;
                lds2(a01, a23, A_sa + (unsigned)((m * HID + k) * 4));
                ffma2(acc2[m], a01, w01); ffma2(acc2[m], a23, w23);
            }
        }
        #pragma unroll
        for (int m = 0; m < 16; m++) res[m] = upk_sum(acc2[m]);
    }
    #pragma unroll
    for (int m = 0; m < 16; m++) {
        float v = fmaxf(res[m], 0.0f);
        #pragma unroll
        for (int a = 0; a < 8; a++)
            out[(size_t)((g0 + m) * 8 + a) * HID + t] = v;
    }
}

// ---------------- launch ---------------------------------------------------
extern "C" void kernel_launch(void* const* d_in, const int* in_sizes, int n_in,
                              void* d_out, int out_size)
{
    const float* hs    = (const float*)d_in[0];
    const float* eps   = (const float*)d_in[1];
    const float* WQ    = (const float*)d_in[2];
    const float* bQ    = (const float*)d_in[3];
    const float* WK    = (const float*)d_in[4];
    const float* bK    = (const float*)d_in[5];
    const float* Wmu   = (const float*)d_in[6];
    const float* bmu   = (const float*)d_in[7];
    const float* Wvar  = (const float*)d_in[8];
    const float* bvar  = (const float*)d_in[9];
    const float* vocab = (const float*)d_in[10];
    const float* Wsum  = (const float*)d_in[11];
    const float* bsum  = (const float*)d_in[12];
    const float* Whead = (const float*)d_in[13];
    const float* bhead = (const float*)d_in[14];
    float* out = (float*)d_out;

    const int smem_main = 12816 * (int)sizeof(float);   // 51264 B
    cudaFuncSetAttribute(main_kernel,
                         cudaFuncAttributeMaxDynamicSharedMemorySize, smem_main);

    sort_kernel<<<COMP, 512>>>(vocab);
    main_kernel<<<B_ROWS / ROWS_PB, 256, smem_main>>>(
        hs, WQ, bQ, WK, bK, Wmu, bmu, Wvar, bvar, vocab, eps);
    tail_kernel<<<NGROUP / 16, 256>>>(Wsum, bsum, Whead, bhead, out);
}